// round 10
// baseline (speedup 1.0000x reference)
#include <cuda_runtime.h>
#include <cstddef>
#include <cstdint>

#define NLAYER 8
#define DMODEL 2048
#define NHEAD 8
#define NKV 2
#define HDIM 256
#define SEQ 4096
#define FFDIM 8192
#define PLDIM 256
#define POS 2048
#define NS 2049
#define NCHUNK 33
#define EPSF 1e-6f

// bulk-GEMV smem: [0,128) 3 mbarriers ; [128,256) red[32] ; [256, 256+DIM*4) xs ;
// then 3*16KB weight ring.
#define RING_B 49152
#define SMEMB_2048 (256 + 2048 * 4 + RING_B)   // 57,600
#define SMEMB_8192 (256 + 8192 * 4 + RING_B)   // 82,176

// ---------------- scratch ----------------
#define OFF_H     0
#define OFF_HN    2048
#define OFF_QKV   4096
#define OFF_Q     7168
#define OFF_KNEW  9216
#define OFF_VNEW  9728
#define OFF_ATTN  10240
#define OFF_ACT   12288              // gelu(g)*u result (8192)
#define OFF_VEC   20480
#define OFF_G2    22528
#define OFF_APART 22784              // 8*33*260 = 68640
#define OFF_PG    91424              // gate raw (8192)
#define OFF_PU    99616              // up raw (8192)
__device__ __align__(16) float g_scratch[99616 + 8192];

// ---------------- helpers ----------------
__device__ __forceinline__ float warp_sum(float v) {
#pragma unroll
    for (int o = 16; o; o >>= 1) v += __shfl_xor_sync(0xffffffffu, v, o);
    return v;
}
__device__ __forceinline__ float warp_max(float v) {
#pragma unroll
    for (int o = 16; o; o >>= 1) v = fmaxf(v, __shfl_xor_sync(0xffffffffu, v, o));
    return v;
}
__device__ __forceinline__ float block_sum(float v) {
    __shared__ float red[16];
    __shared__ float tot;
    int t = threadIdx.x, nw = (int)(blockDim.x >> 5);
    __syncthreads();
    v = warp_sum(v);
    if ((t & 31) == 0) red[t >> 5] = v;
    __syncthreads();
    if (t < 32) {
        float s = (t < nw) ? red[t] : 0.f;
        s = warp_sum(s);
        if (t == 0) tot = s;
    }
    __syncthreads();
    return tot;
}
__device__ __forceinline__ float block_max(float v) {
    __shared__ float red[16];
    __shared__ float tot;
    int t = threadIdx.x, nw = (int)(blockDim.x >> 5);
    __syncthreads();
    v = warp_max(v);
    if ((t & 31) == 0) red[t >> 5] = v;
    __syncthreads();
    if (t < 32) {
        float s = (t < nw) ? red[t] : -3.0e38f;
        s = warp_max(s);
        if (t == 0) tot = s;
    }
    __syncthreads();
    return tot;
}
__device__ __forceinline__ float gelu_t(float x) {
    float x3 = x * x * x;
    return 0.5f * x * (1.f + tanhf(0.7978845608028654f * (x + 0.044715f * x3)));
}
__device__ __forceinline__ float dot4(float4 a, float4 b) {
    return a.x * b.x + a.y * b.y + a.z * b.z + a.w * b.w;
}
__device__ __forceinline__ void pdl_trigger() { cudaTriggerProgrammaticLaunchCompletion(); }
__device__ __forceinline__ void pdl_wait()    { cudaGridDependencySynchronize(); }

__device__ __forceinline__ uint32_t smem_u32(const void* p) {
    return (uint32_t)__cvta_generic_to_shared(p);
}
__device__ __forceinline__ void mbar_init(uint32_t bar, uint32_t cnt) {
    asm volatile("mbarrier.init.shared.b64 [%0], %1;" :: "r"(bar), "r"(cnt) : "memory");
}
__device__ __forceinline__ void mbar_expect_tx(uint32_t bar, uint32_t bytes) {
    asm volatile("mbarrier.arrive.expect_tx.shared.b64 _, [%0], %1;"
                 :: "r"(bar), "r"(bytes) : "memory");
}
__device__ __forceinline__ void mbar_wait(uint32_t bar, uint32_t parity) {
    uint32_t done;
    asm volatile(
        "{\n\t.reg .pred p;\n\t"
        "mbarrier.try_wait.parity.acquire.cta.shared::cta.b64 p, [%1], %2;\n\t"
        "selp.b32 %0, 1, 0, p;\n\t}"
        : "=r"(done) : "r"(bar), "r"(parity) : "memory");
    if (!done) {
        asm volatile(
            "{\n\t.reg .pred P1;\n\t"
            "WL_%=:\n\t"
            "mbarrier.try_wait.parity.acquire.cta.shared::cta.b64 P1, [%0], %1, 0x989680;\n\t"
            "@P1 bra.uni WD_%=;\n\t"
            "bra.uni WL_%=;\n\t"
            "WD_%=:\n\t}"
            :: "r"(bar), "r"(parity) : "memory");
    }
}
// 1D bulk async copy gmem->smem (TMA-class path, bypasses per-thread LSU)
__device__ __forceinline__ void bulk_cp(uint32_t dst_smem, const void* src, uint32_t bytes,
                                        uint32_t bar) {
    asm volatile(
        "cp.async.bulk.shared::cluster.global.mbarrier::complete_tx::bytes "
        "[%0], [%1], %2, [%3];"
        :: "r"(dst_smem), "l"(src), "r"(bytes), "r"(bar) : "memory");
}

// ---------------- bulk GEMV body ----------------
// Block consumes a contiguous 64KB weight tile (16384 floats) = RPB rows of DIM.
// 4 stages x 16KB through a 3-slot ring. yout[r] = W[row r] . x  for r < RPB.
template <int DIM>
__device__ __forceinline__ void gemv_bulk_body(const float* __restrict__ Wtile,
                                               const float* __restrict__ x,
                                               float* __restrict__ yout) {
    constexpr int RPB = 16384 / DIM;        // rows per block
    constexpr int PPR = DIM / 512;          // warp-partials per row
    extern __shared__ float smf[];
    uint64_t* bars = (uint64_t*)smf;        // 3 mbarriers
    float* red = smf + 32;                  // 32 floats
    float* xs  = smf + 64;                  // DIM floats
    float* wring = xs + DIM;                // 3 * 4096 floats
    int t = threadIdx.x, warp = t >> 5, lane = t & 31;
    uint32_t bar0 = smem_u32(bars);

    if (t == 0) {
#pragma unroll
        for (int i = 0; i < 3; i++) mbar_init(bar0 + i * 8, 1);
    }
    __syncthreads();
    if (t == 0) {
#pragma unroll
        for (int s = 0; s < 3; s++) {
            mbar_expect_tx(bar0 + s * 8, 16384u);
            bulk_cp(smem_u32(wring + s * 4096), Wtile + s * 4096, 16384u, bar0 + s * 8);
        }
    }
    pdl_wait();                             // x now valid
    for (int i = t; i < DIM / 4; i += 256) ((float4*)xs)[i] = ((const float4*)x)[i];
    __syncthreads();

#pragma unroll
    for (int s = 0; s < 4; s++) {
        mbar_wait(bar0 + (s % 3) * 8, (uint32_t)(s / 3));
        const float4* wv = (const float4*)(wring + (s % 3) * 4096) + t * 4;
        int col = (s * 4096 + t * 16) % DIM;
        const float4* xv = (const float4*)(xs + col);
        float acc = dot4(wv[0], xv[0]) + dot4(wv[1], xv[1]) +
                    dot4(wv[2], xv[2]) + dot4(wv[3], xv[3]);
        acc = warp_sum(acc);
        if (lane == 0) red[s * 8 + warp] = acc;
        if (s == 0) {
            __syncthreads();                // stage-0 data fully consumed
            if (t == 0) {
                mbar_expect_tx(bar0, 16384u);
                bulk_cp(smem_u32(wring), Wtile + 3 * 4096, 16384u, bar0);
            }
        }
    }
    __syncthreads();
    if (t < RPB) {
        float sum = 0.f;
#pragma unroll
        for (int j = 0; j < PPR; j++) sum += red[t * PPR + j];
        yout[t] = sum;
    }
    pdl_trigger();
}

// ---------------- kernels ----------------

// side-stream KV copy: 4096 blocks * 1024 float4 = kvsz/4 exactly; skips POS rows.
__global__ void k_copy_kv_os(const float4* __restrict__ a, const float4* __restrict__ b,
                             float4* __restrict__ oa, float4* __restrict__ ob) {
    int base = blockIdx.x * 1024 + threadIdx.x;
#pragma unroll
    for (int k = 0; k < 4; k++) {
        int j = base + k * 256;
        float4 av = __ldcs(a + j);
        float4 bv = __ldcs(b + j);
        if (((j >> 6) & (SEQ - 1)) != POS) {
            oa[j] = av;
            ob[j] = bv;
        }
    }
}
__global__ void k_copy_kv_ser(const float4* __restrict__ a, const float4* __restrict__ b,
                              float4* __restrict__ oa, float4* __restrict__ ob, int n4) {
    int i = blockIdx.x * blockDim.x + threadIdx.x;
    int stride = gridDim.x * blockDim.x;
    for (; i < n4; i += stride) {
        float4 av = a[i], bv = b[i];
        if (((i >> 6) & (SEQ - 1)) != POS) { oa[i] = av; ob[i] = bv; }
    }
}

__global__ void k_copy(const float* __restrict__ src, float* __restrict__ dst, int n) {
    pdl_wait();
    int i = blockIdx.x * blockDim.x + threadIdx.x;
    if (i < n) dst[i] = src[i];
    pdl_trigger();
}

// h = hs ; hn = rms(hs)*w
__global__ void k_rms_init(const float* __restrict__ hs, const float* __restrict__ w,
                           float* __restrict__ h, float* __restrict__ hn) {
    int t = threadIdx.x;
    float v[4];
    float ss = 0.f;
#pragma unroll
    for (int i = 0; i < 4; i++) { v[i] = hs[t + 512 * i]; ss += v[i] * v[i]; }
    ss = block_sum(ss);
    float inv = rsqrtf(ss / (float)DMODEL + EPSF);
#pragma unroll
    for (int i = 0; i < 4; i++) {
        h[t + 512 * i] = v[i];
        hn[t + 512 * i] = v[i] * inv * w[t + 512 * i];
    }
    pdl_trigger();
}

// h += rms(raw)*w1 ; hn = rms(h_new)*w2
__global__ void k_rms_add_norm(const float* __restrict__ raw, const float* __restrict__ w1,
                               float* __restrict__ h, const float* __restrict__ w2,
                               float* __restrict__ hn) {
    pdl_wait();
    int t = threadIdx.x;
    float v[4], hv[4];
    float ss = 0.f;
#pragma unroll
    for (int i = 0; i < 4; i++) { v[i] = raw[t + 512 * i]; ss += v[i] * v[i]; }
    ss = block_sum(ss);
    float inv = rsqrtf(ss / (float)DMODEL + EPSF);
    float ss2 = 0.f;
#pragma unroll
    for (int i = 0; i < 4; i++) {
        hv[i] = h[t + 512 * i] + v[i] * inv * w1[t + 512 * i];
        ss2 += hv[i] * hv[i];
    }
    ss2 = block_sum(ss2);
    float inv2 = rsqrtf(ss2 / (float)DMODEL + EPSF);
#pragma unroll
    for (int i = 0; i < 4; i++) {
        h[t + 512 * i] = hv[i];
        hn[t + 512 * i] = hv[i] * inv2 * w2[t + 512 * i];
    }
    pdl_trigger();
}

// h += rms(raw)*w
__global__ void k_rms_add1(const float* __restrict__ raw, const float* __restrict__ w,
                           float* __restrict__ h) {
    pdl_wait();
    int t = threadIdx.x;
    float v[4];
    float ss = 0.f;
#pragma unroll
    for (int i = 0; i < 4; i++) { v[i] = raw[t + 512 * i]; ss += v[i] * v[i]; }
    ss = block_sum(ss);
    float inv = rsqrtf(ss / (float)DMODEL + EPSF);
#pragma unroll
    for (int i = 0; i < 4; i++) h[t + 512 * i] += v[i] * inv * w[t + 512 * i];
    pdl_trigger();
}

// h = (h + rms(raw)*w) * sc[0] ; hn = rms(h_new)*w2
__global__ void k_rms_add_scale_norm(const float* __restrict__ raw, const float* __restrict__ w,
                                     const float* __restrict__ sc, float* __restrict__ h,
                                     const float* __restrict__ w2, float* __restrict__ hn) {
    pdl_wait();
    int t = threadIdx.x;
    float v[4], hv[4];
    float ss = 0.f;
#pragma unroll
    for (int i = 0; i < 4; i++) { v[i] = raw[t + 512 * i]; ss += v[i] * v[i]; }
    ss = block_sum(ss);
    float inv = rsqrtf(ss / (float)DMODEL + EPSF);
    float s = sc[0];
    float ss2 = 0.f;
#pragma unroll
    for (int i = 0; i < 4; i++) {
        hv[i] = (h[t + 512 * i] + v[i] * inv * w[t + 512 * i]) * s;
        ss2 += hv[i] * hv[i];
    }
    ss2 = block_sum(ss2);
    float inv2 = rsqrtf(ss2 / (float)DMODEL + EPSF);
#pragma unroll
    for (int i = 0; i < 4; i++) {
        h[t + 512 * i] = hv[i];
        hn[t + 512 * i] = hv[i] * inv2 * w2[t + 512 * i];
    }
    pdl_trigger();
}

// QKV bulk GEMV: grid 384 (blocks 0-255 Wq, 256-319 Wk, 320-383 Wv)
__global__ void k_qkv_bulk(const float* __restrict__ Wq, const float* __restrict__ Wk,
                           const float* __restrict__ Wv, const float* __restrict__ x,
                           float* __restrict__ y) {
    int b = blockIdx.x;
    const float* Wtile;
    if (b < 256) Wtile = Wq + (size_t)b * 16384;
    else if (b < 320) Wtile = Wk + (size_t)(b - 256) * 16384;
    else Wtile = Wv + (size_t)(b - 320) * 16384;
    gemv_bulk_body<DMODEL>(Wtile, x, y + b * 8);
}

// generic bulk GEMV, DIM=2048 (Wo: grid 256) or 8192 (Wd: grid 1024)
template <int DIM>
__global__ void k_gemv_bulk(const float* __restrict__ W, const float* __restrict__ x,
                            float* __restrict__ y) {
    constexpr int RPB = 16384 / DIM;
    gemv_bulk_body<DIM>(W + (size_t)blockIdx.x * 16384, x, y + blockIdx.x * RPB);
}

// gate+up bulk GEMV: grid 2048 (0-1023 Wg -> pg, 1024-2047 Wu -> pu)
__global__ void k_gateup_bulk(const float* __restrict__ Wg, const float* __restrict__ Wu,
                              const float* __restrict__ x, float* __restrict__ pg,
                              float* __restrict__ pu) {
    int b = blockIdx.x;
    const float* Wtile;
    float* yo;
    if (b < 1024) { Wtile = Wg + (size_t)b * 16384; yo = pg + b * 8; }
    else { Wtile = Wu + (size_t)(b - 1024) * 16384; yo = pu + (b - 1024) * 8; }
    gemv_bulk_body<DMODEL>(Wtile, x, yo);
}

// act[i] = gelu(pg[i]) * pu[i]
__global__ void k_actmul(const float* __restrict__ pg, const float* __restrict__ pu,
                         float* __restrict__ act) {
    pdl_wait();
    int i = blockIdx.x * 256 + threadIdx.x;
    act[i] = gelu_t(pg[i]) * pu[i];
    pdl_trigger();
}

// per-layer gate: block per row (256), y[r] = gelu(W[r].h) * pl[r]
__global__ void k_plg_rowblock(const float* __restrict__ W, const float* __restrict__ x,
                               const float* __restrict__ pl, float* __restrict__ y) {
    int r = blockIdx.x, t = threadIdx.x;
    const float4* wr = (const float4*)(W + (size_t)r * DMODEL);
    float4 a0 = __ldcs(wr + t), a1 = __ldcs(wr + t + 256);
    pdl_wait();
    const float4* xp = (const float4*)x;
    float s = dot4(a0, xp[t]) + dot4(a1, xp[t + 256]);
    s = block_sum(s);
    if (t == 0) y[r] = gelu_t(s) * pl[r];
    pdl_trigger();
}

// small gemv (plp, DIM=256): warp per row, 8 rows/block
__global__ void k_gemv256(const float* __restrict__ W, const float* __restrict__ x,
                          float* __restrict__ y) {
    __shared__ float4 xs[64];
    int t = threadIdx.x;
    int warp = t >> 5, lane = t & 31;
    int row = blockIdx.x * 8 + warp;
    const float4* wr = (const float4*)(W + (size_t)row * 256);
    float4 a0 = __ldcs(wr + lane), a1 = __ldcs(wr + lane + 32);
    pdl_wait();
    if (t < 64) xs[t] = ((const float4*)x)[t];
    __syncthreads();
    float s = dot4(a0, xs[lane]) + dot4(a1, xs[lane + 32]);
    s = warp_sum(s);
    if (lane == 0) y[row] = s;
    pdl_trigger();
}

// per-head rms norm + (qn/kn) scale + rope
__global__ void k_hnr(const float* __restrict__ qkv, const float* __restrict__ qn,
                      const float* __restrict__ kn, const float* __restrict__ cosp,
                      const float* __restrict__ sinp, float* __restrict__ q,
                      float* __restrict__ knew, float* __restrict__ vnew,
                      float* __restrict__ outK_l, float* __restrict__ outV_l) {
    pdl_wait();
    int b = blockIdx.x, t = threadIdx.x;
    float x = qkv[b * 256 + t];
    float ss = block_sum(x * x);
    float inv = rsqrtf(ss / (float)HDIM + EPSF);
    __shared__ float sv[256];
    float val;
    if (b < 8) val = x * inv * qn[t];
    else if (b < 10) val = x * inv * kn[t];
    else val = x * inv;
    sv[t] = val;
    __syncthreads();
    float out;
    if (b < 10) {
        float other = (t < 128) ? -sv[t + 128] : sv[t - 128];
        out = val * cosp[t] + other * sinp[t];
    } else {
        out = val;
    }
    if (b < 8) {
        q[b * 256 + t] = out;
    } else if (b < 10) {
        int kv = b - 8;
        knew[kv * 256 + t] = out;
        outK_l[((size_t)kv * SEQ + POS) * HDIM + t] = out;
    } else {
        int kv = b - 10;
        vnew[kv * 256 + t] = out;
        outV_l[((size_t)kv * SEQ + POS) * HDIM + t] = out;
    }
    pdl_trigger();
}

// flash-style attention partials: grid (8 heads, 33 chunks of 64)
__global__ void k_attn_part(const float* __restrict__ q, const float* __restrict__ Kl,
                            const float* __restrict__ Vl, const float* __restrict__ knew,
                            const float* __restrict__ vnew, float* __restrict__ part) {
    int h = blockIdx.x, c = blockIdx.y, t = threadIdx.x;
    int kv = h >> 2;
    __shared__ float4 qs[64];
    __shared__ float sc[64];
    pdl_wait();
    if (t < 64) qs[t] = ((const float4*)(q + h * 256))[t];
    __syncthreads();
    int warp = t >> 5, lane = t & 31;
    const float* Kbase = Kl + (size_t)kv * SEQ * HDIM;
    const float* knv = knew + kv * HDIM;
    int s0 = c * 64;
#pragma unroll
    for (int i = 0; i < 8; i++) {
        int s = s0 + i * 8 + warp;
        float acc = -3.0e38f;
        if (s <= POS) {
            const float4* kr = (s == POS) ? (const float4*)knv
                                          : (const float4*)(Kbase + (size_t)s * HDIM);
            float4 a0 = __ldcs(kr + lane), a1 = __ldcs(kr + lane + 32);
            acc = dot4(a0, qs[lane]) + dot4(a1, qs[lane + 32]);
            acc = warp_sum(acc);
        }
        if (lane == 0) sc[i * 8 + warp] = acc;
    }
    __syncthreads();
    float mv = (t < 64) ? sc[t] : -3.0e38f;
    float m = block_max(mv);
    float ev = 0.f;
    if (t < 64 && sc[t] > -1.0e38f) ev = __expf(sc[t] - m);
    float l = block_sum(ev);
    if (t < 64) sc[t] = ev;
    __syncthreads();
    const float* Vbase = Vl + (size_t)kv * SEQ * HDIM;
    const float* vnv = vnew + kv * HDIM;
    float o = 0.f;
#pragma unroll 4
    for (int j = 0; j < 64; j++) {
        int s = s0 + j;
        if (s > POS) break;
        const float* vr = (s == POS) ? vnv : (Vbase + (size_t)s * HDIM);
        o += sc[j] * __ldcs(vr + t);
    }
    float* pb = part + ((size_t)h * NCHUNK + c) * 260;
    pb[t] = o;
    if (t == 0) { pb[256] = m; pb[257] = l; }
    pdl_trigger();
}

// combine attention partials: grid 8
__global__ void k_attn_comb(const float* __restrict__ part, float* __restrict__ attn) {
    int h = blockIdx.x, t = threadIdx.x;
    __shared__ float ml[NCHUNK], ll[NCHUNK];
    pdl_wait();
    const float* ph = part + (size_t)h * NCHUNK * 260;
    if (t < NCHUNK) {
        ml[t] = ph[t * 260 + 256];
        ll[t] = ph[t * 260 + 257];
    }
    __syncthreads();
    float M = -3.0e38f;
#pragma unroll
    for (int c = 0; c < NCHUNK; c++) M = fmaxf(M, ml[c]);
    float L = 0.f, o = 0.f;
#pragma unroll
    for (int c = 0; c < NCHUNK; c++) {
        float f = __expf(ml[c] - M);
        L += ll[c] * f;
        o += ph[c * 260 + t] * f;
    }
    attn[h * HDIM + t] = o / L;
    pdl_trigger();
}

// ---------------- host launcher ----------------
template <typename F, typename... Args>
static inline void pdl_launch(F fn, dim3 g, dim3 b, size_t smem, Args... args) {
    cudaLaunchConfig_t cfg = {};
    cfg.gridDim = g;
    cfg.blockDim = b;
    cfg.dynamicSmemBytes = smem;
    cfg.stream = 0;
    cudaLaunchAttribute at[1];
    at[0].id = cudaLaunchAttributeProgrammaticStreamSerialization;
    at[0].val.programmaticStreamSerializationAllowed = 1;
    cfg.attrs = at;
    cfg.numAttrs = 1;
    cudaLaunchKernelEx(&cfg, fn, args...);
}

extern "C" void kernel_launch(void* const* d_in, const int* in_sizes, int n_in,
                              void* d_out, int out_size) {
    const float* hs    = (const float*)d_in[0];
    const float* pls   = (const float*)d_in[3];
    const float* cos_s = (const float*)d_in[4];
    const float* sin_s = (const float*)d_in[5];
    const float* cos_f = (const float*)d_in[6];
    const float* sin_f = (const float*)d_in[7];
    const float* K_in  = (const float*)d_in[8];
    const float* V_in  = (const float*)d_in[9];
    const float* Wq    = (const float*)d_in[10];
    const float* Wk    = (const float*)d_in[11];
    const float* Wv    = (const float*)d_in[12];
    const float* Wo    = (const float*)d_in[13];
    const float* qn    = (const float*)d_in[14];
    const float* kn    = (const float*)d_in[15];
    const float* ln_in   = (const float*)d_in[16];
    const float* ln_pa   = (const float*)d_in[17];
    const float* ln_pre  = (const float*)d_in[18];
    const float* ln_post = (const float*)d_in[19];
    const float* ln_pl   = (const float*)d_in[20];
    const float* Wg    = (const float*)d_in[21];
    const float* Wu    = (const float*)d_in[22];
    const float* Wd    = (const float*)d_in[23];
    const float* Wplg  = (const float*)d_in[24];
    const float* Wplp  = (const float*)d_in[25];
    const float* lsc   = (const float*)d_in[26];

    float* out = (float*)d_out;
    const size_t kvsz = (size_t)NLAYER * NKV * SEQ * HDIM;
    float* outK = out + DMODEL;
    float* outV = outK + kvsz;

    float* sb = nullptr;
    cudaGetSymbolAddress((void**)&sb, g_scratch);
    float* b_h     = sb + OFF_H;
    float* b_hn    = sb + OFF_HN;
    float* b_qkv   = sb + OFF_QKV;
    float* b_q     = sb + OFF_Q;
    float* b_knew  = sb + OFF_KNEW;
    float* b_vnew  = sb + OFF_VNEW;
    float* b_attn  = sb + OFF_ATTN;
    float* b_act   = sb + OFF_ACT;
    float* b_vec   = sb + OFF_VEC;
    float* b_g2    = sb + OFF_G2;
    float* b_apart = sb + OFF_APART;
    float* b_pg    = sb + OFF_PG;
    float* b_pu    = sb + OFF_PU;

    static bool attrs_done = false;
    if (!attrs_done) {
        cudaFuncSetAttribute(k_qkv_bulk, cudaFuncAttributeMaxDynamicSharedMemorySize, SMEMB_2048);
        cudaFuncSetAttribute(k_gemv_bulk<2048>, cudaFuncAttributeMaxDynamicSharedMemorySize, SMEMB_2048);
        cudaFuncSetAttribute(k_gateup_bulk, cudaFuncAttributeMaxDynamicSharedMemorySize, SMEMB_2048);
        cudaFuncSetAttribute(k_gemv_bulk<8192>, cudaFuncAttributeMaxDynamicSharedMemorySize, SMEMB_8192);
        attrs_done = true;
    }
    static cudaStream_t s2 = nullptr;
    static cudaEvent_t evF = nullptr, evJ = nullptr;
    static bool side_ok = false;
    if (!s2) {
        int lo = 0, hi = 0;
        cudaDeviceGetStreamPriorityRange(&lo, &hi);
        side_ok = (cudaStreamCreateWithPriority(&s2, cudaStreamNonBlocking, lo) == cudaSuccess) &&
                  (cudaEventCreateWithFlags(&evF, cudaEventDisableTiming) == cudaSuccess) &&
                  (cudaEventCreateWithFlags(&evJ, cudaEventDisableTiming) == cudaSuccess);
    }

    if (side_ok) {
        cudaEventRecord(evF, 0);
        cudaStreamWaitEvent(s2, evF, 0);
        k_copy_kv_os<<<4096, 256, 0, s2>>>((const float4*)K_in, (const float4*)V_in,
                                           (float4*)outK, (float4*)outV);
        cudaEventRecord(evJ, s2);
    } else {
        k_copy_kv_ser<<<1184, 256>>>((const float4*)K_in, (const float4*)V_in,
                                     (float4*)outK, (float4*)outV, (int)(kvsz / 4));
    }

    pdl_launch(k_rms_init, dim3(1), dim3(512), 0, hs, ln_in, b_h, b_hn);

    for (int l = 0; l < NLAYER; l++) {
        const float* Wq_l = Wq + (size_t)l * 2048 * 2048;
        const float* Wk_l = Wk + (size_t)l * 512 * 2048;
        const float* Wv_l = Wv + (size_t)l * 512 * 2048;
        const float* Wo_l = Wo + (size_t)l * 2048 * 2048;
        const float* Wg_l = Wg + (size_t)l * 8192 * 2048;
        const float* Wu_l = Wu + (size_t)l * 8192 * 2048;
        const float* Wd_l = Wd + (size_t)l * 2048 * 8192;
        const float* Wplg_l = Wplg + (size_t)l * 256 * 2048;
        const float* Wplp_l = Wplp + (size_t)l * 2048 * 256;
        const float* K_l = K_in + (size_t)l * NKV * SEQ * HDIM;
        const float* V_l = V_in + (size_t)l * NKV * SEQ * HDIM;
        float* outK_l = outK + (size_t)l * NKV * SEQ * HDIM;
        float* outV_l = outV + (size_t)l * NKV * SEQ * HDIM;
        bool full = ((l + 1) % 5) == 0;
        const float* cp = full ? cos_f : cos_s;
        const float* sp = full ? sin_f : sin_s;
        const float* ln_in_next = ln_in + ((l + 1 < NLAYER) ? (l + 1) : 0) * DMODEL;

        // attention block
        pdl_launch(k_qkv_bulk, dim3(384), dim3(256), (size_t)SMEMB_2048,
                   Wq_l, Wk_l, Wv_l, (const float*)b_hn, b_qkv);
        pdl_launch(k_hnr, dim3(12), dim3(256), 0, (const float*)b_qkv,
                   qn + l * HDIM, kn + l * HDIM, cp, sp,
                   b_q, b_knew, b_vnew, outK_l, outV_l);
        pdl_launch(k_attn_part, dim3(8, NCHUNK), dim3(256), 0, (const float*)b_q,
                   K_l, V_l, (const float*)b_knew, (const float*)b_vnew, b_apart);
        pdl_launch(k_attn_comb, dim3(8), dim3(256), 0, (const float*)b_apart, b_attn);
        pdl_launch(k_gemv_bulk<2048>, dim3(256), dim3(256), (size_t)SMEMB_2048,
                   Wo_l, (const float*)b_attn, b_vec);
        pdl_launch(k_rms_add_norm, dim3(1), dim3(512), 0, (const float*)b_vec,
                   ln_pa + l * DMODEL, b_h, ln_pre + l * DMODEL, b_hn);
        // MLP block
        pdl_launch(k_gateup_bulk, dim3(2048), dim3(256), (size_t)SMEMB_2048,
                   Wg_l, Wu_l, (const float*)b_hn, b_pg, b_pu);
        pdl_launch(k_actmul, dim3(32), dim3(256), 0, (const float*)b_pg,
                   (const float*)b_pu, b_act);
        pdl_launch(k_gemv_bulk<8192>, dim3(1024), dim3(256), (size_t)SMEMB_8192,
                   Wd_l, (const float*)b_act, b_vec);
        pdl_launch(k_rms_add1, dim3(1), dim3(512), 0, (const float*)b_vec,
                   ln_post + l * DMODEL, b_h);
        // per-layer block
        pdl_launch(k_plg_rowblock, dim3(256), dim3(256), 0, Wplg_l,
                   (const float*)b_h, pls + l * PLDIM, b_g2);
        pdl_launch(k_gemv256, dim3(256), dim3(256), 0, Wplp_l,
                   (const float*)b_g2, b_vec);
        pdl_launch(k_rms_add_scale_norm, dim3(1), dim3(512), 0, (const float*)b_vec,
                   ln_pl + l * DMODEL, lsc + l, b_h, ln_in_next, b_hn);
    }

    if (side_ok) cudaStreamWaitEvent(0, evJ, 0);
    pdl_launch(k_copy, dim3(8), dim3(256), 0, (const float*)b_h, out, DMODEL);
}

// round 11
// speedup vs baseline: 1.1005x; 1.1005x over previous
#include <cuda_runtime.h>
#include <cstddef>
#include <cstdint>

#define NLAYER 8
#define DMODEL 2048
#define NHEAD 8
#define NKV 2
#define HDIM 256
#define SEQ 4096
#define FFDIM 8192
#define PLDIM 256
#define POS 2048
#define NS 2049
#define NCHUNK 33
#define EPSF 1e-6f

// dynamic smem layout for cp.async GEMV kernels (in float4):
#define XS4   512
#define WS4   3072
#define SS4   1024
#define SMEMB ((XS4 + WS4) * 16 + 64)

// ---------------- scratch ----------------
#define OFF_H     0
#define OFF_HN    2048
#define OFF_QKV   4096
#define OFF_Q     7168
#define OFF_KNEW  9216
#define OFF_VNEW  9728
#define OFF_ATTN  10240
#define OFF_ACT   12288
#define OFF_VEC   20480
#define OFF_G2    22528
#define OFF_APART 22784              // 8*33*260 = 68640
#define OFF_WPART 91424              // Wd split-4 partials (4*2048)
#define OFF_SINK  99616              // prefetch sink (256)
__device__ __align__(16) float g_scratch[99616 + 256];

// ---------------- helpers ----------------
__device__ __forceinline__ float warp_sum(float v) {
#pragma unroll
    for (int o = 16; o; o >>= 1) v += __shfl_xor_sync(0xffffffffu, v, o);
    return v;
}
__device__ __forceinline__ float warp_max(float v) {
#pragma unroll
    for (int o = 16; o; o >>= 1) v = fmaxf(v, __shfl_xor_sync(0xffffffffu, v, o));
    return v;
}
__device__ __forceinline__ float block_sum(float v) {
    __shared__ float red[16];
    __shared__ float tot;
    int t = threadIdx.x, nw = (int)(blockDim.x >> 5);
    __syncthreads();
    v = warp_sum(v);
    if ((t & 31) == 0) red[t >> 5] = v;
    __syncthreads();
    if (t < 32) {
        float s = (t < nw) ? red[t] : 0.f;
        s = warp_sum(s);
        if (t == 0) tot = s;
    }
    __syncthreads();
    return tot;
}
__device__ __forceinline__ float block_max(float v) {
    __shared__ float red[16];
    __shared__ float tot;
    int t = threadIdx.x, nw = (int)(blockDim.x >> 5);
    __syncthreads();
    v = warp_max(v);
    if ((t & 31) == 0) red[t >> 5] = v;
    __syncthreads();
    if (t < 32) {
        float s = (t < nw) ? red[t] : -3.0e38f;
        s = warp_max(s);
        if (t == 0) tot = s;
    }
    __syncthreads();
    return tot;
}
__device__ __forceinline__ float gelu_t(float x) {
    float x3 = x * x * x;
    return 0.5f * x * (1.f + tanhf(0.7978845608028654f * (x + 0.044715f * x3)));
}
__device__ __forceinline__ float dot4(float4 a, float4 b) {
    return a.x * b.x + a.y * b.y + a.z * b.z + a.w * b.w;
}
__device__ __forceinline__ void pdl_trigger() { cudaTriggerProgrammaticLaunchCompletion(); }
__device__ __forceinline__ void pdl_wait()    { cudaGridDependencySynchronize(); }

// ---------------- cp.async machinery ----------------
__device__ __forceinline__ void cp16(float4* sptr, const float4* gptr) {
    uint32_t sa = (uint32_t)__cvta_generic_to_shared(sptr);
    asm volatile("cp.async.cg.shared.global [%0], [%1], 16;\n" :: "r"(sa), "l"(gptr) : "memory");
}
__device__ __forceinline__ void cp_commit() {
    asm volatile("cp.async.commit_group;\n" ::: "memory");
}
__device__ __forceinline__ void rs_issue(const float4* gp, float4* wstage, int lane) {
#pragma unroll
    for (int i = 0; i < 4; i++) cp16(wstage + lane + 32 * i, gp + lane + 32 * i);
    cp_commit();
}
template <int NST>
__device__ __forceinline__ void rs_prologue(const float4* gp, float4* wswarp, int lane) {
#pragma unroll
    for (int s = 0; s < (NST < 3 ? NST : 3); s++)
        rs_issue(gp + s * 128, wswarp + s * SS4, lane);
}
template <int NST>
__device__ __forceinline__ float rs_loop(const float4* gp, float4* wswarp,
                                         const float4* xsw, int lane) {
    float acc = 0.f;
#pragma unroll
    for (int s = 0; s < NST; s++) {
        int rem = NST - 1 - s;
        if (rem >= 2)      asm volatile("cp.async.wait_group 2;\n" ::: "memory");
        else if (rem == 1) asm volatile("cp.async.wait_group 1;\n" ::: "memory");
        else               asm volatile("cp.async.wait_group 0;\n" ::: "memory");
        const float4* wstage = wswarp + (s % 3) * SS4;
#pragma unroll
        for (int i = 0; i < 4; i++)
            acc += dot4(wstage[lane + 32 * i], xsw[s * 128 + lane + 32 * i]);
        if (s + 3 < NST)
            rs_issue(gp + (s + 3) * 128, wswarp + ((s + 3) % 3) * SS4, lane);
    }
    return acc;
}

// ---------------- kernels ----------------

// L2 prefetch: one-shot blocks, each reads 4096 float4 (64KB) with __ldcg and
// dumps a sum into a garbage sink (never read; races harmless).
__global__ void k_prefetch(const float4* __restrict__ w, float* __restrict__ sink) {
    int base = blockIdx.x * 4096 + threadIdx.x;
    float4 s4 = make_float4(0.f, 0.f, 0.f, 0.f);
#pragma unroll
    for (int i = 0; i < 16; i++) {
        float4 v = __ldcg(w + base + i * 256);
        s4.x += v.x; s4.y += v.y; s4.z += v.z; s4.w += v.w;
    }
    sink[threadIdx.x] = s4.x + s4.y + s4.z + s4.w;
}

// side-stream KV copy: 4096 blocks * 1024 float4 = kvsz/4 exactly; skips POS rows.
__global__ void k_copy_kv_os(const float4* __restrict__ a, const float4* __restrict__ b,
                             float4* __restrict__ oa, float4* __restrict__ ob) {
    int base = blockIdx.x * 1024 + threadIdx.x;
#pragma unroll
    for (int k = 0; k < 4; k++) {
        int j = base + k * 256;
        float4 av = __ldcs(a + j);
        float4 bv = __ldcs(b + j);
        if (((j >> 6) & (SEQ - 1)) != POS) {
            oa[j] = av;
            ob[j] = bv;
        }
    }
}
__global__ void k_copy_kv_ser(const float4* __restrict__ a, const float4* __restrict__ b,
                              float4* __restrict__ oa, float4* __restrict__ ob, int n4) {
    int i = blockIdx.x * blockDim.x + threadIdx.x;
    int stride = gridDim.x * blockDim.x;
    for (; i < n4; i += stride) {
        float4 av = a[i], bv = b[i];
        if (((i >> 6) & (SEQ - 1)) != POS) { oa[i] = av; ob[i] = bv; }
    }
}

__global__ void k_copy(const float* __restrict__ src, float* __restrict__ dst, int n) {
    pdl_wait();
    int i = blockIdx.x * blockDim.x + threadIdx.x;
    if (i < n) dst[i] = src[i];
    pdl_trigger();
}

// h = hs ; hn = rms(hs)*w
__global__ void k_rms_init(const float* __restrict__ hs, const float* __restrict__ w,
                           float* __restrict__ h, float* __restrict__ hn) {
    int t = threadIdx.x;
    float v[4];
    float ss = 0.f;
#pragma unroll
    for (int i = 0; i < 4; i++) { v[i] = hs[t + 512 * i]; ss += v[i] * v[i]; }
    ss = block_sum(ss);
    float inv = rsqrtf(ss / (float)DMODEL + EPSF);
#pragma unroll
    for (int i = 0; i < 4; i++) {
        h[t + 512 * i] = v[i];
        hn[t + 512 * i] = v[i] * inv * w[t + 512 * i];
    }
    pdl_trigger();
}

// h += rms(sum partials)*w1 ; hn = rms(h_new)*w2
template <int NSPLIT>
__global__ void k_rms_add_norm_p(const float* __restrict__ part, const float* __restrict__ w1,
                                 float* __restrict__ h, const float* __restrict__ w2,
                                 float* __restrict__ hn) {
    pdl_wait();
    int t = threadIdx.x;
    float v[4], hv[4];
    float ss = 0.f;
#pragma unroll
    for (int i = 0; i < 4; i++) {
        int j = t + 512 * i;
        float r = 0.f;
#pragma unroll
        for (int s = 0; s < NSPLIT; s++) r += part[s * DMODEL + j];
        v[i] = r;
        ss += r * r;
    }
    ss = block_sum(ss);
    float inv = rsqrtf(ss / (float)DMODEL + EPSF);
    float ss2 = 0.f;
#pragma unroll
    for (int i = 0; i < 4; i++) {
        hv[i] = h[t + 512 * i] + v[i] * inv * w1[t + 512 * i];
        ss2 += hv[i] * hv[i];
    }
    ss2 = block_sum(ss2);
    float inv2 = rsqrtf(ss2 / (float)DMODEL + EPSF);
#pragma unroll
    for (int i = 0; i < 4; i++) {
        h[t + 512 * i] = hv[i];
        hn[t + 512 * i] = hv[i] * inv2 * w2[t + 512 * i];
    }
    pdl_trigger();
}

// h += rms(sum partials)*w
template <int NSPLIT>
__global__ void k_rms_add(const float* __restrict__ part, const float* __restrict__ w,
                          float* __restrict__ h) {
    pdl_wait();
    int t = threadIdx.x;
    float v[4];
    float ss = 0.f;
#pragma unroll
    for (int i = 0; i < 4; i++) {
        int j = t + 512 * i;
        float r = 0.f;
#pragma unroll
        for (int s = 0; s < NSPLIT; s++) r += part[s * DMODEL + j];
        v[i] = r;
        ss += r * r;
    }
    ss = block_sum(ss);
    float inv = rsqrtf(ss / (float)DMODEL + EPSF);
#pragma unroll
    for (int i = 0; i < 4; i++) h[t + 512 * i] += v[i] * inv * w[t + 512 * i];
    pdl_trigger();
}

// h = (h + rms(raw)*w) * sc[0] ; hn = rms(h_new)*w2
__global__ void k_rms_add_scale_norm(const float* __restrict__ raw, const float* __restrict__ w,
                                     const float* __restrict__ sc, float* __restrict__ h,
                                     const float* __restrict__ w2, float* __restrict__ hn) {
    pdl_wait();
    int t = threadIdx.x;
    float v[4], hv[4];
    float ss = 0.f;
#pragma unroll
    for (int i = 0; i < 4; i++) { v[i] = raw[t + 512 * i]; ss += v[i] * v[i]; }
    ss = block_sum(ss);
    float inv = rsqrtf(ss / (float)DMODEL + EPSF);
    float s = sc[0];
    float ss2 = 0.f;
#pragma unroll
    for (int i = 0; i < 4; i++) {
        hv[i] = (h[t + 512 * i] + v[i] * inv * w[t + 512 * i]) * s;
        ss2 += hv[i] * hv[i];
    }
    ss2 = block_sum(ss2);
    float inv2 = rsqrtf(ss2 / (float)DMODEL + EPSF);
#pragma unroll
    for (int i = 0; i < 4; i++) {
        h[t + 512 * i] = hv[i];
        hn[t + 512 * i] = hv[i] * inv2 * w2[t + 512 * i];
    }
    pdl_trigger();
}

// fused q/k/v projection, cp.async + PDL
__global__ void k_qkv_cp(const float* __restrict__ Wq, const float* __restrict__ Wk,
                         const float* __restrict__ Wv, const float* __restrict__ x,
                         float* __restrict__ y) {
    extern __shared__ float4 sm[];
    float4* xs = sm;
    float4* ws = sm + XS4;
    int t = threadIdx.x, warp = t >> 5, lane = t & 31;
    int row = blockIdx.x * 8 + warp;
    const float* W;
    int r;
    if (row < 2048) { W = Wq; r = row; }
    else if (row < 2560) { W = Wk; r = row - 2048; }
    else { W = Wv; r = row - 2560; }
    const float4* gp = (const float4*)(W + (size_t)r * DMODEL);
    float4* wswarp = ws + warp * 128;
    rs_prologue<4>(gp, wswarp, lane);
    pdl_wait();
    xs[t] = ((const float4*)x)[t];
    xs[t + 256] = ((const float4*)x)[t + 256];
    __syncthreads();
    float acc = rs_loop<4>(gp, wswarp, xs, lane);
    acc = warp_sum(acc);
    if (lane == 0) y[row] = acc;
    pdl_trigger();
}

// generic full-K (2048) GEMV + PDL (Wo: grid 256)
__global__ void k_gemv_cp(const float* __restrict__ W, const float* __restrict__ x,
                          float* __restrict__ y) {
    extern __shared__ float4 sm[];
    float4* xs = sm;
    float4* ws = sm + XS4;
    int t = threadIdx.x, warp = t >> 5, lane = t & 31;
    int row = blockIdx.x * 8 + warp;
    const float4* gp = (const float4*)(W + (size_t)row * DMODEL);
    float4* wswarp = ws + warp * 128;
    rs_prologue<4>(gp, wswarp, lane);
    pdl_wait();
    xs[t] = ((const float4*)x)[t];
    xs[t + 256] = ((const float4*)x)[t + 256];
    __syncthreads();
    float acc = rs_loop<4>(gp, wswarp, xs, lane);
    acc = warp_sum(acc);
    if (lane == 0) y[row] = acc;
    pdl_trigger();
}

// fused gate/up + PDL: grid 2048, block = 4 output rows
__global__ void k_gateup_cp(const float* __restrict__ Wg, const float* __restrict__ Wu,
                            const float* __restrict__ x, float* __restrict__ act) {
    extern __shared__ float4 sm[];
    float4* xs = sm;
    float4* ws = sm + XS4;
    float* red = (float*)(sm + XS4 + WS4);
    int t = threadIdx.x, warp = t >> 5, lane = t & 31;
    int row = blockIdx.x * 4 + (warp & 3);
    const float* W = (warp < 4) ? Wg : Wu;
    const float4* gp = (const float4*)(W + (size_t)row * DMODEL);
    float4* wswarp = ws + warp * 128;
    rs_prologue<4>(gp, wswarp, lane);
    pdl_wait();
    xs[t] = ((const float4*)x)[t];
    xs[t + 256] = ((const float4*)x)[t + 256];
    __syncthreads();
    float acc = rs_loop<4>(gp, wswarp, xs, lane);
    acc = warp_sum(acc);
    if (lane == 0) red[warp] = acc;
    __syncthreads();
    if (t < 4) act[blockIdx.x * 4 + t] = gelu_t(red[t]) * red[t + 4];
    pdl_trigger();
}

// Wd split-4 + PDL: grid 1024
__global__ void k_wd_cp(const float* __restrict__ W, const float* __restrict__ x,
                        float* __restrict__ ypart) {
    extern __shared__ float4 sm[];
    float4* xs = sm;
    float4* ws = sm + XS4;
    int t = threadIdx.x, warp = t >> 5, lane = t & 31;
    int grp = blockIdx.x & 255;
    int c = blockIdx.x >> 8;
    int row = grp * 8 + warp;
    const float4* gp = (const float4*)(W + (size_t)row * FFDIM + c * 2048);
    float4* wswarp = ws + warp * 128;
    rs_prologue<4>(gp, wswarp, lane);
    pdl_wait();
    const float4* xp = (const float4*)(x + c * 2048);
    xs[t] = xp[t];
    xs[t + 256] = xp[t + 256];
    __syncthreads();
    float acc = rs_loop<4>(gp, wswarp, xs, lane);
    acc = warp_sum(acc);
    if (lane == 0) ypart[c * 2048 + row] = acc;
    pdl_trigger();
}

// per-layer gate + PDL: block per row (256)
__global__ void k_plg_rowblock(const float* __restrict__ W, const float* __restrict__ x,
                               const float* __restrict__ pl, float* __restrict__ y) {
    int r = blockIdx.x, t = threadIdx.x;
    const float4* wr = (const float4*)(W + (size_t)r * DMODEL);
    float4 a0 = __ldcs(wr + t), a1 = __ldcs(wr + t + 256);
    pdl_wait();
    const float4* xp = (const float4*)x;
    float s = dot4(a0, xp[t]) + dot4(a1, xp[t + 256]);
    s = block_sum(s);
    if (t == 0) y[r] = gelu_t(s) * pl[r];
    pdl_trigger();
}

// small gemv (plp, DIM=256) + PDL
__global__ void k_gemv256(const float* __restrict__ W, const float* __restrict__ x,
                          float* __restrict__ y) {
    __shared__ float4 xs[64];
    int t = threadIdx.x;
    int warp = t >> 5, lane = t & 31;
    int row = blockIdx.x * 8 + warp;
    const float4* wr = (const float4*)(W + (size_t)row * 256);
    float4 a0 = __ldcs(wr + lane), a1 = __ldcs(wr + lane + 32);
    pdl_wait();
    if (t < 64) xs[t] = ((const float4*)x)[t];
    __syncthreads();
    float s = dot4(a0, xs[lane]) + dot4(a1, xs[lane + 32]);
    s = warp_sum(s);
    if (lane == 0) y[row] = s;
    pdl_trigger();
}

// per-head rms norm + (qn/kn) scale + rope + PDL
__global__ void k_hnr(const float* __restrict__ qkv, const float* __restrict__ qn,
                      const float* __restrict__ kn, const float* __restrict__ cosp,
                      const float* __restrict__ sinp, float* __restrict__ q,
                      float* __restrict__ knew, float* __restrict__ vnew,
                      float* __restrict__ outK_l, float* __restrict__ outV_l) {
    pdl_wait();
    int b = blockIdx.x, t = threadIdx.x;
    float x = qkv[b * 256 + t];
    float ss = block_sum(x * x);
    float inv = rsqrtf(ss / (float)HDIM + EPSF);
    __shared__ float sv[256];
    float val;
    if (b < 8) val = x * inv * qn[t];
    else if (b < 10) val = x * inv * kn[t];
    else val = x * inv;
    sv[t] = val;
    __syncthreads();
    float out;
    if (b < 10) {
        float other = (t < 128) ? -sv[t + 128] : sv[t - 128];
        out = val * cosp[t] + other * sinp[t];
    } else {
        out = val;
    }
    if (b < 8) {
        q[b * 256 + t] = out;
    } else if (b < 10) {
        int kv = b - 8;
        knew[kv * 256 + t] = out;
        outK_l[((size_t)kv * SEQ + POS) * HDIM + t] = out;
    } else {
        int kv = b - 10;
        vnew[kv * 256 + t] = out;
        outV_l[((size_t)kv * SEQ + POS) * HDIM + t] = out;
    }
    pdl_trigger();
}

// flash-style attention partials: grid (8 heads, 33 chunks of 64)
__global__ void k_attn_part(const float* __restrict__ q, const float* __restrict__ Kl,
                            const float* __restrict__ Vl, const float* __restrict__ knew,
                            const float* __restrict__ vnew, float* __restrict__ part) {
    int h = blockIdx.x, c = blockIdx.y, t = threadIdx.x;
    int kv = h >> 2;
    __shared__ float4 qs[64];
    __shared__ float sc[64];
    pdl_wait();
    if (t < 64) qs[t] = ((const float4*)(q + h * 256))[t];
    __syncthreads();
    int warp = t >> 5, lane = t & 31;
    const float* Kbase = Kl + (size_t)kv * SEQ * HDIM;
    const float* knv = knew + kv * HDIM;
    int s0 = c * 64;
#pragma unroll
    for (int i = 0; i < 8; i++) {
        int s = s0 + i * 8 + warp;
        float acc = -3.0e38f;
        if (s <= POS) {
            const float4* kr = (s == POS) ? (const float4*)knv
                                          : (const float4*)(Kbase + (size_t)s * HDIM);
            float4 a0 = __ldcs(kr + lane), a1 = __ldcs(kr + lane + 32);
            acc = dot4(a0, qs[lane]) + dot4(a1, qs[lane + 32]);
            acc = warp_sum(acc);
        }
        if (lane == 0) sc[i * 8 + warp] = acc;
    }
    __syncthreads();
    float mv = (t < 64) ? sc[t] : -3.0e38f;
    float m = block_max(mv);
    float ev = 0.f;
    if (t < 64 && sc[t] > -1.0e38f) ev = __expf(sc[t] - m);
    float l = block_sum(ev);
    if (t < 64) sc[t] = ev;
    __syncthreads();
    const float* Vbase = Vl + (size_t)kv * SEQ * HDIM;
    const float* vnv = vnew + kv * HDIM;
    float o = 0.f;
#pragma unroll 4
    for (int j = 0; j < 64; j++) {
        int s = s0 + j;
        if (s > POS) break;
        const float* vr = (s == POS) ? vnv : (Vbase + (size_t)s * HDIM);
        o += sc[j] * __ldcs(vr + t);
    }
    float* pb = part + ((size_t)h * NCHUNK + c) * 260;
    pb[t] = o;
    if (t == 0) { pb[256] = m; pb[257] = l; }
    pdl_trigger();
}

// combine attention partials: grid 8
__global__ void k_attn_comb(const float* __restrict__ part, float* __restrict__ attn) {
    int h = blockIdx.x, t = threadIdx.x;
    __shared__ float ml[NCHUNK], ll[NCHUNK];
    pdl_wait();
    const float* ph = part + (size_t)h * NCHUNK * 260;
    if (t < NCHUNK) {
        ml[t] = ph[t * 260 + 256];
        ll[t] = ph[t * 260 + 257];
    }
    __syncthreads();
    float M = -3.0e38f;
#pragma unroll
    for (int c = 0; c < NCHUNK; c++) M = fmaxf(M, ml[c]);
    float L = 0.f, o = 0.f;
#pragma unroll
    for (int c = 0; c < NCHUNK; c++) {
        float f = __expf(ml[c] - M);
        L += ll[c] * f;
        o += ph[c * 260 + t] * f;
    }
    attn[h * HDIM + t] = o / L;
    pdl_trigger();
}

// ---------------- host launcher ----------------
template <typename F, typename... Args>
static inline void pdl_launch(F fn, dim3 g, dim3 b, size_t smem, Args... args) {
    cudaLaunchConfig_t cfg = {};
    cfg.gridDim = g;
    cfg.blockDim = b;
    cfg.dynamicSmemBytes = smem;
    cfg.stream = 0;
    cudaLaunchAttribute at[1];
    at[0].id = cudaLaunchAttributeProgrammaticStreamSerialization;
    at[0].val.programmaticStreamSerializationAllowed = 1;
    cfg.attrs = at;
    cfg.numAttrs = 1;
    cudaLaunchKernelEx(&cfg, fn, args...);
}

extern "C" void kernel_launch(void* const* d_in, const int* in_sizes, int n_in,
                              void* d_out, int out_size) {
    const float* hs    = (const float*)d_in[0];
    const float* pls   = (const float*)d_in[3];
    const float* cos_s = (const float*)d_in[4];
    const float* sin_s = (const float*)d_in[5];
    const float* cos_f = (const float*)d_in[6];
    const float* sin_f = (const float*)d_in[7];
    const float* K_in  = (const float*)d_in[8];
    const float* V_in  = (const float*)d_in[9];
    const float* Wq    = (const float*)d_in[10];
    const float* Wk    = (const float*)d_in[11];
    const float* Wv    = (const float*)d_in[12];
    const float* Wo    = (const float*)d_in[13];
    const float* qn    = (const float*)d_in[14];
    const float* kn    = (const float*)d_in[15];
    const float* ln_in   = (const float*)d_in[16];
    const float* ln_pa   = (const float*)d_in[17];
    const float* ln_pre  = (const float*)d_in[18];
    const float* ln_post = (const float*)d_in[19];
    const float* ln_pl   = (const float*)d_in[20];
    const float* Wg    = (const float*)d_in[21];
    const float* Wu    = (const float*)d_in[22];
    const float* Wd    = (const float*)d_in[23];
    const float* Wplg  = (const float*)d_in[24];
    const float* Wplp  = (const float*)d_in[25];
    const float* lsc   = (const float*)d_in[26];

    float* out = (float*)d_out;
    const size_t kvsz = (size_t)NLAYER * NKV * SEQ * HDIM;
    float* outK = out + DMODEL;
    float* outV = outK + kvsz;

    float* sb = nullptr;
    cudaGetSymbolAddress((void**)&sb, g_scratch);
    float* b_h     = sb + OFF_H;
    float* b_hn    = sb + OFF_HN;
    float* b_qkv   = sb + OFF_QKV;
    float* b_q     = sb + OFF_Q;
    float* b_knew  = sb + OFF_KNEW;
    float* b_vnew  = sb + OFF_VNEW;
    float* b_attn  = sb + OFF_ATTN;
    float* b_act   = sb + OFF_ACT;
    float* b_vec   = sb + OFF_VEC;
    float* b_g2    = sb + OFF_G2;
    float* b_apart = sb + OFF_APART;
    float* b_wpart = sb + OFF_WPART;
    float* b_sink  = sb + OFF_SINK;

    static bool attrs_done = false;
    if (!attrs_done) {
        cudaFuncSetAttribute(k_qkv_cp, cudaFuncAttributeMaxDynamicSharedMemorySize, SMEMB);
        cudaFuncSetAttribute(k_gemv_cp, cudaFuncAttributeMaxDynamicSharedMemorySize, SMEMB);
        cudaFuncSetAttribute(k_gateup_cp, cudaFuncAttributeMaxDynamicSharedMemorySize, SMEMB);
        cudaFuncSetAttribute(k_wd_cp, cudaFuncAttributeMaxDynamicSharedMemorySize, SMEMB);
        attrs_done = true;
    }
    // streams/events (created once, outside capture on the correctness run)
    static cudaStream_t s2 = nullptr, s3 = nullptr;
    static cudaEvent_t evF = nullptr, evJ2 = nullptr, evJ3 = nullptr;
    static cudaEvent_t evA[NLAYER], evB[NLAYER];
    static bool side_ok = false;
    if (!s2) {
        int lo = 0, hi = 0;
        cudaDeviceGetStreamPriorityRange(&lo, &hi);
        bool ok = (cudaStreamCreateWithPriority(&s2, cudaStreamNonBlocking, lo) == cudaSuccess) &&
                  (cudaStreamCreateWithPriority(&s3, cudaStreamNonBlocking, lo) == cudaSuccess) &&
                  (cudaEventCreateWithFlags(&evF, cudaEventDisableTiming) == cudaSuccess) &&
                  (cudaEventCreateWithFlags(&evJ2, cudaEventDisableTiming) == cudaSuccess) &&
                  (cudaEventCreateWithFlags(&evJ3, cudaEventDisableTiming) == cudaSuccess);
        for (int l = 0; l < NLAYER && ok; l++) {
            ok = (cudaEventCreateWithFlags(&evA[l], cudaEventDisableTiming) == cudaSuccess) &&
                 (cudaEventCreateWithFlags(&evB[l], cudaEventDisableTiming) == cudaSuccess);
        }
        side_ok = ok;
    }

    if (side_ok) {
        // fork both side streams from the origin stream
        cudaEventRecord(evF, 0);
        cudaStreamWaitEvent(s2, evF, 0);
        cudaStreamWaitEvent(s3, evF, 0);
        // KV copy on s3 (skips POS rows — written exclusively by k_hnr)
        k_copy_kv_os<<<4096, 256, 0, s3>>>((const float4*)K_in, (const float4*)V_in,
                                           (float4*)outK, (float4*)outV);
        cudaEventRecord(evJ3, s3);
    } else {
        k_copy_kv_ser<<<1184, 256>>>((const float4*)K_in, (const float4*)V_in,
                                     (float4*)outK, (float4*)outV, (int)(kvsz / 4));
    }

    pdl_launch(k_rms_init, dim3(1), dim3(512), 0, hs, ln_in, b_h, b_hn);

    for (int l = 0; l < NLAYER; l++) {
        const float* Wq_l = Wq + (size_t)l * 2048 * 2048;
        const float* Wk_l = Wk + (size_t)l * 512 * 2048;
        const float* Wv_l = Wv + (size_t)l * 512 * 2048;
        const float* Wo_l = Wo + (size_t)l * 2048 * 2048;
        const float* Wg_l = Wg + (size_t)l * 8192 * 2048;
        const float* Wu_l = Wu + (size_t)l * 8192 * 2048;
        const float* Wd_l = Wd + (size_t)l * 2048 * 8192;
        const float* Wplg_l = Wplg + (size_t)l * 256 * 2048;
        const float* Wplp_l = Wplp + (size_t)l * 2048 * 256;
        const float* K_l = K_in + (size_t)l * NKV * SEQ * HDIM;
        const float* V_l = V_in + (size_t)l * NKV * SEQ * HDIM;
        float* outK_l = outK + (size_t)l * NKV * SEQ * HDIM;
        float* outV_l = outV + (size_t)l * NKV * SEQ * HDIM;
        bool full = ((l + 1) % 5) == 0;
        const float* cp = full ? cos_f : cos_s;
        const float* sp = full ? sin_f : sin_s;
        const float* ln_in_next = ln_in + ((l + 1 < NLAYER) ? (l + 1) : 0) * DMODEL;

        // prefetch Wg/Wu into L2 during attention phase (throttled by evA)
        if (side_ok) {
            cudaEventRecord(evA[l], 0);
            cudaStreamWaitEvent(s2, evA[l], 0);
            k_prefetch<<<1024, 256, 0, s2>>>((const float4*)Wg_l, b_sink);
            k_prefetch<<<1024, 256, 0, s2>>>((const float4*)Wu_l, b_sink);
        }

        // attention block
        pdl_launch(k_qkv_cp, dim3(384), dim3(256), SMEMB, Wq_l, Wk_l, Wv_l,
                   (const float*)b_hn, b_qkv);
        pdl_launch(k_hnr, dim3(12), dim3(256), 0, (const float*)b_qkv,
                   qn + l * HDIM, kn + l * HDIM, cp, sp,
                   b_q, b_knew, b_vnew, outK_l, outV_l);
        pdl_launch(k_attn_part, dim3(8, NCHUNK), dim3(256), 0, (const float*)b_q,
                   K_l, V_l, (const float*)b_knew, (const float*)b_vnew, b_apart);
        pdl_launch(k_attn_comb, dim3(8), dim3(256), 0, (const float*)b_apart, b_attn);
        pdl_launch(k_gemv_cp, dim3(256), dim3(256), SMEMB, Wo_l,
                   (const float*)b_attn, b_vec);
        pdl_launch(k_rms_add_norm_p<1>, dim3(1), dim3(512), 0, (const float*)b_vec,
                   ln_pa + l * DMODEL, b_h, ln_pre + l * DMODEL, b_hn);

        // prefetch Wd during gate/up (throttled by evB)
        if (side_ok) {
            cudaEventRecord(evB[l], 0);
            cudaStreamWaitEvent(s2, evB[l], 0);
            k_prefetch<<<1024, 256, 0, s2>>>((const float4*)Wd_l, b_sink);
        }

        // MLP block
        pdl_launch(k_gateup_cp, dim3(2048), dim3(256), SMEMB, Wg_l, Wu_l,
                   (const float*)b_hn, b_act);
        pdl_launch(k_wd_cp, dim3(1024), dim3(256), SMEMB, Wd_l,
                   (const float*)b_act, b_wpart);
        pdl_launch(k_rms_add<4>, dim3(1), dim3(512), 0, (const float*)b_wpart,
                   ln_post + l * DMODEL, b_h);
        // per-layer block
        pdl_launch(k_plg_rowblock, dim3(256), dim3(256), 0, Wplg_l,
                   (const float*)b_h, pls + l * PLDIM, b_g2);
        pdl_launch(k_gemv256, dim3(256), dim3(256), 0, Wplp_l,
                   (const float*)b_g2, b_vec);
        pdl_launch(k_rms_add_scale_norm, dim3(1), dim3(512), 0, (const float*)b_vec,
                   ln_pl + l * DMODEL, lsc + l, b_h, ln_in_next, b_hn);
    }

    // join both side streams, then final hidden state
    if (side_ok) {
        cudaEventRecord(evJ2, s2);
        cudaStreamWaitEvent(0, evJ2, 0);
        cudaStreamWaitEvent(0, evJ3, 0);
    }
    pdl_launch(k_copy, dim3(8), dim3(256), 0, (const float*)b_h, out, DMODEL);
}

// round 13
// speedup vs baseline: 1.5200x; 1.3812x over previous
#include <cuda_runtime.h>
#include <cstddef>
#include <cstdint>

#define NLAYER 8
#define DMODEL 2048
#define NHEAD 8
#define NKV 2
#define HDIM 256
#define SEQ 4096
#define FFDIM 8192
#define PLDIM 256
#define POS 2048
#define NS 2049
#define NCHUNK 33
#define EPSF 1e-6f

// dynamic smem layout for cp.async GEMV kernels (in float4):
#define XS4   512
#define WS4   3072
#define SS4   1024
#define SMEMB ((XS4 + WS4) * 16 + 64)

// ---------------- scratch ----------------
#define OFF_H     0
#define OFF_HN    2048
#define OFF_QKV   4096
#define OFF_ATTN  10240
#define OFF_ACT   12288
#define OFF_VEC   20480
#define OFF_G2    22528
#define OFF_APART 22784              // 8*33*260 = 68640
#define OFF_WPART 91424              // Wd split-4 partials (4*2048)
#define OFF_CTR   99616              // 16 counters (as uint)
__device__ __align__(16) float g_scratch[99616 + 16];

// ---------------- helpers ----------------
__device__ __forceinline__ float warp_sum(float v) {
#pragma unroll
    for (int o = 16; o; o >>= 1) v += __shfl_xor_sync(0xffffffffu, v, o);
    return v;
}
__device__ __forceinline__ float block_sum(float v) {
    __shared__ float red[16];
    __shared__ float tot;
    int t = threadIdx.x, nw = (int)(blockDim.x >> 5);
    __syncthreads();
    v = warp_sum(v);
    if ((t & 31) == 0) red[t >> 5] = v;
    __syncthreads();
    if (t < 32) {
        float s = (t < nw) ? red[t] : 0.f;
        s = warp_sum(s);
        if (t == 0) tot = s;
    }
    __syncthreads();
    return tot;
}
__device__ __forceinline__ float gelu_t(float x) {
    float x3 = x * x * x;
    return 0.5f * x * (1.f + tanhf(0.7978845608028654f * (x + 0.044715f * x3)));
}
__device__ __forceinline__ float dot4(float4 a, float4 b) {
    return a.x * b.x + a.y * b.y + a.z * b.z + a.w * b.w;
}
__device__ __forceinline__ void pdl_trigger() { cudaTriggerProgrammaticLaunchCompletion(); }
__device__ __forceinline__ void pdl_wait()    { cudaGridDependencySynchronize(); }

// ---------------- cp.async machinery ----------------
__device__ __forceinline__ void cp16(float4* sptr, const float4* gptr) {
    uint32_t sa = (uint32_t)__cvta_generic_to_shared(sptr);
    asm volatile("cp.async.cg.shared.global [%0], [%1], 16;\n" :: "r"(sa), "l"(gptr) : "memory");
}
__device__ __forceinline__ void cp_commit() {
    asm volatile("cp.async.commit_group;\n" ::: "memory");
}
__device__ __forceinline__ void rs_issue(const float4* gp, float4* wstage, int lane) {
#pragma unroll
    for (int i = 0; i < 4; i++) cp16(wstage + lane + 32 * i, gp + lane + 32 * i);
    cp_commit();
}
template <int NST>
__device__ __forceinline__ void rs_prologue(const float4* gp, float4* wswarp, int lane) {
#pragma unroll
    for (int s = 0; s < (NST < 3 ? NST : 3); s++)
        rs_issue(gp + s * 128, wswarp + s * SS4, lane);
}
template <int NST>
__device__ __forceinline__ float rs_loop(const float4* gp, float4* wswarp,
                                         const float4* xsw, int lane) {
    float acc = 0.f;
#pragma unroll
    for (int s = 0; s < NST; s++) {
        int rem = NST - 1 - s;
        if (rem >= 2)      asm volatile("cp.async.wait_group 2;\n" ::: "memory");
        else if (rem == 1) asm volatile("cp.async.wait_group 1;\n" ::: "memory");
        else               asm volatile("cp.async.wait_group 0;\n" ::: "memory");
        const float4* wstage = wswarp + (s % 3) * SS4;
#pragma unroll
        for (int i = 0; i < 4; i++)
            acc += dot4(wstage[lane + 32 * i], xsw[s * 128 + lane + 32 * i]);
        if (s + 3 < NST)
            rs_issue(gp + (s + 3) * 128, wswarp + ((s + 3) % 3) * SS4, lane);
    }
    return acc;
}

// ---------------- last-block epilogues (256 threads, 8 elems/thread) ----------------
__device__ __forceinline__ void epi_add_norm(const float* __restrict__ vec,
                                             const float* __restrict__ w1, float* __restrict__ h,
                                             const float* __restrict__ w2, float* __restrict__ hn) {
    int t = threadIdx.x;
    float v[8], hv[8];
    float ss = 0.f;
#pragma unroll
    for (int i = 0; i < 8; i++) { v[i] = vec[t + 256 * i]; ss += v[i] * v[i]; }
    ss = block_sum(ss);
    float inv = rsqrtf(ss / (float)DMODEL + EPSF);
    float ss2 = 0.f;
#pragma unroll
    for (int i = 0; i < 8; i++) {
        hv[i] = h[t + 256 * i] + v[i] * inv * w1[t + 256 * i];
        ss2 += hv[i] * hv[i];
    }
    ss2 = block_sum(ss2);
    float inv2 = rsqrtf(ss2 / (float)DMODEL + EPSF);
#pragma unroll
    for (int i = 0; i < 8; i++) {
        h[t + 256 * i] = hv[i];
        hn[t + 256 * i] = hv[i] * inv2 * w2[t + 256 * i];
    }
}
__device__ __forceinline__ void epi_add4(const float* __restrict__ part,
                                         const float* __restrict__ w, float* __restrict__ h) {
    int t = threadIdx.x;
    float v[8];
    float ss = 0.f;
#pragma unroll
    for (int i = 0; i < 8; i++) {
        int j = t + 256 * i;
        float r = part[j] + part[2048 + j] + part[4096 + j] + part[6144 + j];
        v[i] = r;
        ss += r * r;
    }
    ss = block_sum(ss);
    float inv = rsqrtf(ss / (float)DMODEL + EPSF);
#pragma unroll
    for (int i = 0; i < 8; i++) h[t + 256 * i] += v[i] * inv * w[t + 256 * i];
}
__device__ __forceinline__ void epi_add_scale_norm(const float* __restrict__ vec,
                                                   const float* __restrict__ w,
                                                   const float* __restrict__ sc,
                                                   float* __restrict__ h,
                                                   const float* __restrict__ w2,
                                                   float* __restrict__ hn) {
    int t = threadIdx.x;
    float v[8], hv[8];
    float ss = 0.f;
#pragma unroll
    for (int i = 0; i < 8; i++) { v[i] = vec[t + 256 * i]; ss += v[i] * v[i]; }
    ss = block_sum(ss);
    float inv = rsqrtf(ss / (float)DMODEL + EPSF);
    float s = sc[0];
    float ss2 = 0.f;
#pragma unroll
    for (int i = 0; i < 8; i++) {
        hv[i] = (h[t + 256 * i] + v[i] * inv * w[t + 256 * i]) * s;
        ss2 += hv[i] * hv[i];
    }
    ss2 = block_sum(ss2);
    float inv2 = rsqrtf(ss2 / (float)DMODEL + EPSF);
#pragma unroll
    for (int i = 0; i < 8; i++) {
        h[t + 256 * i] = hv[i];
        hn[t + 256 * i] = hv[i] * inv2 * w2[t + 256 * i];
    }
}
// true in the last block of the grid (threadFenceReduction pattern)
__device__ __forceinline__ bool last_block(unsigned int* ctr, unsigned int nblocks) {
    __shared__ unsigned int lastf;
    __threadfence();
    if (threadIdx.x == 0) lastf = (atomicAdd(ctr, 1u) == nblocks - 1u) ? 1u : 0u;
    __syncthreads();
    return lastf != 0u;
}

// ---------------- kernels ----------------

// side-stream KV copy: 4096 blocks * 1024 float4 = kvsz/4 exactly; skips POS rows.
__global__ void k_copy_kv_os(const float4* __restrict__ a, const float4* __restrict__ b,
                             float4* __restrict__ oa, float4* __restrict__ ob) {
    int base = blockIdx.x * 1024 + threadIdx.x;
#pragma unroll
    for (int k = 0; k < 4; k++) {
        int j = base + k * 256;
        float4 av = __ldcs(a + j);
        float4 bv = __ldcs(b + j);
        if (((j >> 6) & (SEQ - 1)) != POS) {
            oa[j] = av;
            ob[j] = bv;
        }
    }
}
__global__ void k_copy_kv_ser(const float4* __restrict__ a, const float4* __restrict__ b,
                              float4* __restrict__ oa, float4* __restrict__ ob, int n4) {
    int i = blockIdx.x * blockDim.x + threadIdx.x;
    int stride = gridDim.x * blockDim.x;
    for (; i < n4; i += stride) {
        float4 av = a[i], bv = b[i];
        if (((i >> 6) & (SEQ - 1)) != POS) { oa[i] = av; ob[i] = bv; }
    }
}

__global__ void k_copy(const float* __restrict__ src, float* __restrict__ dst, int n) {
    pdl_wait();
    int i = blockIdx.x * blockDim.x + threadIdx.x;
    if (i < n) dst[i] = src[i];
    pdl_trigger();
}

// h = hs ; hn = rms(hs)*w   (1 block, 512 threads)
__global__ void k_rms_init(const float* __restrict__ hs, const float* __restrict__ w,
                           float* __restrict__ h, float* __restrict__ hn) {
    int t = threadIdx.x;
    float v[4];
    float ss = 0.f;
#pragma unroll
    for (int i = 0; i < 4; i++) { v[i] = hs[t + 512 * i]; ss += v[i] * v[i]; }
    ss = block_sum(ss);
    float inv = rsqrtf(ss / (float)DMODEL + EPSF);
#pragma unroll
    for (int i = 0; i < 4; i++) {
        h[t + 512 * i] = v[i];
        hn[t + 512 * i] = v[i] * inv * w[t + 512 * i];
    }
    pdl_trigger();
}

// fused q/k/v projection, cp.async + PDL: grid 384
__global__ void k_qkv_cp(const float* __restrict__ Wq, const float* __restrict__ Wk,
                         const float* __restrict__ Wv, const float* __restrict__ x,
                         float* __restrict__ y) {
    extern __shared__ float4 sm[];
    float4* xs = sm;
    float4* ws = sm + XS4;
    int t = threadIdx.x, warp = t >> 5, lane = t & 31;
    int row = blockIdx.x * 8 + warp;
    const float* W;
    int r;
    if (row < 2048) { W = Wq; r = row; }
    else if (row < 2560) { W = Wk; r = row - 2048; }
    else { W = Wv; r = row - 2560; }
    const float4* gp = (const float4*)(W + (size_t)r * DMODEL);
    float4* wswarp = ws + warp * 128;
    rs_prologue<4>(gp, wswarp, lane);
    pdl_wait();
    xs[t] = ((const float4*)x)[t];
    xs[t + 256] = ((const float4*)x)[t + 256];
    __syncthreads();
    float acc = rs_loop<4>(gp, wswarp, xs, lane);
    acc = warp_sum(acc);
    if (lane == 0) y[row] = acc;
    pdl_trigger();
}

// fused attention: q norm+rope per block; chunk-32 blocks build k/v + write POS
// cache rows; chunk flash partials; per-head last block combines into attn.
// grid (8, 33), 256 threads.
__global__ void k_attn_fused(const float* __restrict__ qkv, const float* __restrict__ qn,
                             const float* __restrict__ kn, const float* __restrict__ cosp,
                             const float* __restrict__ sinp, const float* __restrict__ Kl,
                             const float* __restrict__ Vl, float* __restrict__ outK_l,
                             float* __restrict__ outV_l, float* __restrict__ part,
                             float* __restrict__ attn, unsigned int* __restrict__ ctr) {
    int h = blockIdx.x, c = blockIdx.y, t = threadIdx.x;
    int kv = h >> 2;
    __shared__ float4 qs4[64];
    float* qsf = (float*)qs4;
    __shared__ float qa[256];
    __shared__ float ks[256];
    __shared__ float vs[256];
    __shared__ float sc[64];
    __shared__ float cml[NCHUNK], cll[NCHUNK];
    pdl_wait();
    // q head norm + rope (all blocks)
    float xq = qkv[h * 256 + t];
    float ssq = block_sum(xq * xq);
    float invq = rsqrtf(ssq / (float)HDIM + EPSF);
    float vq = xq * invq * qn[t];
    qa[t] = vq;
    __syncthreads();
    float oth = (t < 128) ? -qa[t + 128] : qa[t - 128];
    float qr = vq * cosp[t] + oth * sinp[t];
    __syncthreads();                 // all qa reads done before reuse
    qsf[t] = qr;
    if (c == NCHUNK - 1) {
        // knew (norm*kn + rope)
        float xk = qkv[2048 + kv * 256 + t];
        float ssk = block_sum(xk * xk);   // entry sync also publishes qsf
        float vk = xk * rsqrtf(ssk / (float)HDIM + EPSF) * kn[t];
        qa[t] = vk;
        __syncthreads();
        float othk = (t < 128) ? -qa[t + 128] : qa[t - 128];
        ks[t] = vk * cosp[t] + othk * sinp[t];
        // vnew (rms only)
        float xv = qkv[2560 + kv * 256 + t];
        float ssv = block_sum(xv * xv);
        vs[t] = xv * rsqrtf(ssv / (float)HDIM + EPSF);
        __syncthreads();
        if (h == 0 || h == 4) {
            outK_l[((size_t)kv * SEQ + POS) * HDIM + t] = ks[t];
            outV_l[((size_t)kv * SEQ + POS) * HDIM + t] = vs[t];
        }
    } else {
        __syncthreads();             // qsf visible
    }
    // scores for this chunk (POS row read from SHARED, cache rows via __ldcs)
    int warp = t >> 5, lane = t & 31;
    const float* Kbase = Kl + (size_t)kv * SEQ * HDIM;
    int s0 = c * 64;
#pragma unroll
    for (int i = 0; i < 8; i++) {
        int s = s0 + i * 8 + warp;
        float acc = -3.0e38f;
        if (s <= POS) {
            float4 a0, a1;
            if (s == POS) {
                a0 = ((const float4*)ks)[lane];
                a1 = ((const float4*)ks)[lane + 32];
            } else {
                const float4* kr = (const float4*)(Kbase + (size_t)s * HDIM);
                a0 = __ldcs(kr + lane);
                a1 = __ldcs(kr + lane + 32);
            }
            acc = dot4(a0, qs4[lane]) + dot4(a1, qs4[lane + 32]);
            acc = warp_sum(acc);
        }
        if (lane == 0) sc[i * 8 + warp] = acc;
    }
    __syncthreads();
    // local softmax over 64
    float mv = (t < 64) ? sc[t] : -3.0e38f;
#pragma unroll
    for (int o = 16; o; o >>= 1) mv = fmaxf(mv, __shfl_xor_sync(0xffffffffu, mv, o));
    __shared__ float mred[8];
    if ((t & 31) == 0) mred[t >> 5] = mv;
    __syncthreads();
    float m = fmaxf(fmaxf(mred[0], mred[1]), -3.0e38f);
    float ev = 0.f;
    if (t < 64 && sc[t] > -1.0e38f) ev = __expf(sc[t] - m);
    float l = block_sum(ev);
    if (t < 64) sc[t] = ev;
    __syncthreads();
    // partial o (POS row from shared, others global streaming)
    const float* Vbase = Vl + (size_t)kv * SEQ * HDIM;
    float o = 0.f;
    int jmax = (s0 + 63 <= POS) ? 64 : (POS - s0 + 1);
#pragma unroll 4
    for (int j = 0; j < jmax; j++) {
        int s = s0 + j;
        float vval = (s == POS) ? vs[t] : __ldcs(Vbase + (size_t)s * HDIM + t);
        o += sc[j] * vval;
    }
    float* pb = part + ((size_t)h * NCHUNK + c) * 260;
    pb[t] = o;
    if (t == 0) { pb[256] = m; pb[257] = l; }
    // last block of this head combines
    if (last_block(ctr + h, NCHUNK)) {
        const float* ph = part + (size_t)h * NCHUNK * 260;
        if (t < NCHUNK) {
            cml[t] = ph[t * 260 + 256];
            cll[t] = ph[t * 260 + 257];
        }
        __syncthreads();
        float M = -3.0e38f;
#pragma unroll
        for (int cc = 0; cc < NCHUNK; cc++) M = fmaxf(M, cml[cc]);
        float L = 0.f, oo = 0.f;
#pragma unroll
        for (int cc = 0; cc < NCHUNK; cc++) {
            float f = __expf(cml[cc] - M);
            L += cll[cc] * f;
            oo += ph[cc * 260 + t] * f;
        }
        attn[h * HDIM + t] = oo / L;
        if (t == 0) ctr[h] = 0u;
    }
    pdl_trigger();
}

// Wo GEMV (grid 256) + last-block rms_add_norm epilogue
__global__ void k_gemv_wo(const float* __restrict__ W, const float* __restrict__ x,
                          float* __restrict__ y, const float* __restrict__ w1,
                          float* __restrict__ h, const float* __restrict__ w2,
                          float* __restrict__ hn, unsigned int* __restrict__ ctr) {
    extern __shared__ float4 sm[];
    float4* xs = sm;
    float4* ws = sm + XS4;
    int t = threadIdx.x, warp = t >> 5, lane = t & 31;
    int row = blockIdx.x * 8 + warp;
    const float4* gp = (const float4*)(W + (size_t)row * DMODEL);
    float4* wswarp = ws + warp * 128;
    rs_prologue<4>(gp, wswarp, lane);
    pdl_wait();
    xs[t] = ((const float4*)x)[t];
    xs[t + 256] = ((const float4*)x)[t + 256];
    __syncthreads();
    float acc = rs_loop<4>(gp, wswarp, xs, lane);
    acc = warp_sum(acc);
    if (lane == 0) y[row] = acc;
    if (last_block(ctr, 256u)) {
        epi_add_norm(y, w1, h, w2, hn);
        if (t == 0) *ctr = 0u;
    }
    pdl_trigger();
}

// fused gate/up + PDL: grid 2048, block = 4 output rows
__global__ void k_gateup_cp(const float* __restrict__ Wg, const float* __restrict__ Wu,
                            const float* __restrict__ x, float* __restrict__ act) {
    extern __shared__ float4 sm[];
    float4* xs = sm;
    float4* ws = sm + XS4;
    float* red = (float*)(sm + XS4 + WS4);
    int t = threadIdx.x, warp = t >> 5, lane = t & 31;
    int row = blockIdx.x * 4 + (warp & 3);
    const float* W = (warp < 4) ? Wg : Wu;
    const float4* gp = (const float4*)(W + (size_t)row * DMODEL);
    float4* wswarp = ws + warp * 128;
    rs_prologue<4>(gp, wswarp, lane);
    pdl_wait();
    xs[t] = ((const float4*)x)[t];
    xs[t + 256] = ((const float4*)x)[t + 256];
    __syncthreads();
    float acc = rs_loop<4>(gp, wswarp, xs, lane);
    acc = warp_sum(acc);
    if (lane == 0) red[warp] = acc;
    __syncthreads();
    if (t < 4) act[blockIdx.x * 4 + t] = gelu_t(red[t]) * red[t + 4];
    pdl_trigger();
}

// Wd split-4 (grid 1024) + last-block rms_add epilogue
__global__ void k_wd_cp(const float* __restrict__ W, const float* __restrict__ x,
                        float* __restrict__ ypart, const float* __restrict__ w,
                        float* __restrict__ h, unsigned int* __restrict__ ctr) {
    extern __shared__ float4 sm[];
    float4* xs = sm;
    float4* ws = sm + XS4;
    int t = threadIdx.x, warp = t >> 5, lane = t & 31;
    int grp = blockIdx.x & 255;
    int c = blockIdx.x >> 8;
    int row = grp * 8 + warp;
    const float4* gp = (const float4*)(W + (size_t)row * FFDIM + c * 2048);
    float4* wswarp = ws + warp * 128;
    rs_prologue<4>(gp, wswarp, lane);
    pdl_wait();
    const float4* xp = (const float4*)(x + c * 2048);
    xs[t] = xp[t];
    xs[t + 256] = xp[t + 256];
    __syncthreads();
    float acc = rs_loop<4>(gp, wswarp, xs, lane);
    acc = warp_sum(acc);
    if (lane == 0) ypart[c * 2048 + row] = acc;
    if (last_block(ctr, 1024u)) {
        epi_add4(ypart, w, h);
        if (t == 0) *ctr = 0u;
    }
    pdl_trigger();
}

// per-layer gate + PDL: block per row (256)
__global__ void k_plg_rowblock(const float* __restrict__ W, const float* __restrict__ x,
                               const float* __restrict__ pl, float* __restrict__ y) {
    int r = blockIdx.x, t = threadIdx.x;
    const float4* wr = (const float4*)(W + (size_t)r * DMODEL);
    float4 a0 = __ldcs(wr + t), a1 = __ldcs(wr + t + 256);
    pdl_wait();
    const float4* xp = (const float4*)x;
    float s = dot4(a0, xp[t]) + dot4(a1, xp[t + 256]);
    s = block_sum(s);
    if (t == 0) y[r] = gelu_t(s) * pl[r];
    pdl_trigger();
}

// plp GEMV (grid 256, warp per row) + last-block rms_add_scale_norm epilogue
__global__ void k_plp(const float* __restrict__ W, const float* __restrict__ x,
                      float* __restrict__ y, const float* __restrict__ w,
                      const float* __restrict__ sc, float* __restrict__ h,
                      const float* __restrict__ w2, float* __restrict__ hn,
                      unsigned int* __restrict__ ctr) {
    __shared__ float4 xs[64];
    int t = threadIdx.x;
    int warp = t >> 5, lane = t & 31;
    int row = blockIdx.x * 8 + warp;
    const float4* wr = (const float4*)(W + (size_t)row * 256);
    float4 a0 = __ldcs(wr + lane), a1 = __ldcs(wr + lane + 32);
    pdl_wait();
    if (t < 64) xs[t] = ((const float4*)x)[t];
    __syncthreads();
    float s = dot4(a0, xs[lane]) + dot4(a1, xs[lane + 32]);
    s = warp_sum(s);
    if (lane == 0) y[row] = s;
    if (last_block(ctr, 256u)) {
        epi_add_scale_norm(y, w, sc, h, w2, hn);
        if (t == 0) *ctr = 0u;
    }
    pdl_trigger();
}

// ---------------- host launcher ----------------
template <typename F, typename... Args>
static inline void pdl_launch(F fn, dim3 g, dim3 b, size_t smem, Args... args) {
    cudaLaunchConfig_t cfg = {};
    cfg.gridDim = g;
    cfg.blockDim = b;
    cfg.dynamicSmemBytes = smem;
    cfg.stream = 0;
    cudaLaunchAttribute at[1];
    at[0].id = cudaLaunchAttributeProgrammaticStreamSerialization;
    at[0].val.programmaticStreamSerializationAllowed = 1;
    cfg.attrs = at;
    cfg.numAttrs = 1;
    cudaLaunchKernelEx(&cfg, fn, args...);
}

extern "C" void kernel_launch(void* const* d_in, const int* in_sizes, int n_in,
                              void* d_out, int out_size) {
    const float* hs    = (const float*)d_in[0];
    const float* pls   = (const float*)d_in[3];
    const float* cos_s = (const float*)d_in[4];
    const float* sin_s = (const float*)d_in[5];
    const float* cos_f = (const float*)d_in[6];
    const float* sin_f = (const float*)d_in[7];
    const float* K_in  = (const float*)d_in[8];
    const float* V_in  = (const float*)d_in[9];
    const float* Wq    = (const float*)d_in[10];
    const float* Wk    = (const float*)d_in[11];
    const float* Wv    = (const float*)d_in[12];
    const float* Wo    = (const float*)d_in[13];
    const float* qn    = (const float*)d_in[14];
    const float* kn    = (const float*)d_in[15];
    const float* ln_in   = (const float*)d_in[16];
    const float* ln_pa   = (const float*)d_in[17];
    const float* ln_pre  = (const float*)d_in[18];
    const float* ln_post = (const float*)d_in[19];
    const float* ln_pl   = (const float*)d_in[20];
    const float* Wg    = (const float*)d_in[21];
    const float* Wu    = (const float*)d_in[22];
    const float* Wd    = (const float*)d_in[23];
    const float* Wplg  = (const float*)d_in[24];
    const float* Wplp  = (const float*)d_in[25];
    const float* lsc   = (const float*)d_in[26];

    float* out = (float*)d_out;
    const size_t kvsz = (size_t)NLAYER * NKV * SEQ * HDIM;
    float* outK = out + DMODEL;
    float* outV = outK + kvsz;

    float* sb = nullptr;
    cudaGetSymbolAddress((void**)&sb, g_scratch);
    float* b_h     = sb + OFF_H;
    float* b_hn    = sb + OFF_HN;
    float* b_qkv   = sb + OFF_QKV;
    float* b_attn  = sb + OFF_ATTN;
    float* b_act   = sb + OFF_ACT;
    float* b_vec   = sb + OFF_VEC;
    float* b_g2    = sb + OFF_G2;
    float* b_apart = sb + OFF_APART;
    float* b_wpart = sb + OFF_WPART;
    unsigned int* ctr = (unsigned int*)(sb + OFF_CTR);
    unsigned int* ctrA   = ctr;          // 8 per-head counters
    unsigned int* ctrWo  = ctr + 8;
    unsigned int* ctrWd  = ctr + 9;
    unsigned int* ctrPlp = ctr + 10;

    static bool attrs_done = false;
    if (!attrs_done) {
        cudaFuncSetAttribute(k_qkv_cp, cudaFuncAttributeMaxDynamicSharedMemorySize, SMEMB);
        cudaFuncSetAttribute(k_gemv_wo, cudaFuncAttributeMaxDynamicSharedMemorySize, SMEMB);
        cudaFuncSetAttribute(k_gateup_cp, cudaFuncAttributeMaxDynamicSharedMemorySize, SMEMB);
        cudaFuncSetAttribute(k_wd_cp, cudaFuncAttributeMaxDynamicSharedMemorySize, SMEMB);
        attrs_done = true;
    }
    static cudaStream_t s2 = nullptr;
    static cudaEvent_t evF = nullptr, evJ = nullptr;
    static bool side_ok = false;
    if (!s2) {
        int lo = 0, hi = 0;
        cudaDeviceGetStreamPriorityRange(&lo, &hi);
        side_ok = (cudaStreamCreateWithPriority(&s2, cudaStreamNonBlocking, lo) == cudaSuccess) &&
                  (cudaEventCreateWithFlags(&evF, cudaEventDisableTiming) == cudaSuccess) &&
                  (cudaEventCreateWithFlags(&evJ, cudaEventDisableTiming) == cudaSuccess);
    }

    if (side_ok) {
        cudaEventRecord(evF, 0);
        cudaStreamWaitEvent(s2, evF, 0);
        k_copy_kv_os<<<4096, 256, 0, s2>>>((const float4*)K_in, (const float4*)V_in,
                                           (float4*)outK, (float4*)outV);
        cudaEventRecord(evJ, s2);
    } else {
        k_copy_kv_ser<<<1184, 256>>>((const float4*)K_in, (const float4*)V_in,
                                     (float4*)outK, (float4*)outV, (int)(kvsz / 4));
    }

    pdl_launch(k_rms_init, dim3(1), dim3(512), 0, hs, ln_in, b_h, b_hn);

    for (int l = 0; l < NLAYER; l++) {
        const float* Wq_l = Wq + (size_t)l * 2048 * 2048;
        const float* Wk_l = Wk + (size_t)l * 512 * 2048;
        const float* Wv_l = Wv + (size_t)l * 512 * 2048;
        const float* Wo_l = Wo + (size_t)l * 2048 * 2048;
        const float* Wg_l = Wg + (size_t)l * 8192 * 2048;
        const float* Wu_l = Wu + (size_t)l * 8192 * 2048;
        const float* Wd_l = Wd + (size_t)l * 2048 * 8192;
        const float* Wplg_l = Wplg + (size_t)l * 256 * 2048;
        const float* Wplp_l = Wplp + (size_t)l * 2048 * 256;
        const float* K_l = K_in + (size_t)l * NKV * SEQ * HDIM;
        const float* V_l = V_in + (size_t)l * NKV * SEQ * HDIM;
        float* outK_l = outK + (size_t)l * NKV * SEQ * HDIM;
        float* outV_l = outV + (size_t)l * NKV * SEQ * HDIM;
        bool full = ((l + 1) % 5) == 0;
        const float* cp = full ? cos_f : cos_s;
        const float* sp = full ? sin_f : sin_s;
        const float* ln_in_next = ln_in + ((l + 1 < NLAYER) ? (l + 1) : 0) * DMODEL;

        pdl_launch(k_qkv_cp, dim3(384), dim3(256), SMEMB, Wq_l, Wk_l, Wv_l,
                   (const float*)b_hn, b_qkv);
        pdl_launch(k_attn_fused, dim3(8, NCHUNK), dim3(256), 0, (const float*)b_qkv,
                   qn + l * HDIM, kn + l * HDIM, cp, sp, K_l, V_l,
                   outK_l, outV_l, b_apart, b_attn, ctrA);
        pdl_launch(k_gemv_wo, dim3(256), dim3(256), SMEMB, Wo_l, (const float*)b_attn,
                   b_vec, ln_pa + l * DMODEL, b_h, ln_pre + l * DMODEL, b_hn, ctrWo);
        pdl_launch(k_gateup_cp, dim3(2048), dim3(256), SMEMB, Wg_l, Wu_l,
                   (const float*)b_hn, b_act);
        pdl_launch(k_wd_cp, dim3(1024), dim3(256), SMEMB, Wd_l, (const float*)b_act,
                   b_wpart, ln_post + l * DMODEL, b_h, ctrWd);
        pdl_launch(k_plg_rowblock, dim3(256), dim3(256), 0, Wplg_l,
                   (const float*)b_h, pls + l * PLDIM, b_g2);
        pdl_launch(k_plp, dim3(256), dim3(256), 0, Wplp_l, (const float*)b_g2,
                   b_vec, ln_pl + l * DMODEL, lsc + l, b_h, ln_in_next, b_hn, ctrPlp);
    }

    if (side_ok) cudaStreamWaitEvent(0, evJ, 0);
    pdl_launch(k_copy, dim3(8), dim3(256), 0, (const float*)b_h, out, DMODEL);
}